// round 15
// baseline (speedup 1.0000x reference)
#include <cuda_runtime.h>
#include <cuda_fp16.h>
#include <cstdint>

#define T_STEPS 100
#define N_IN    784
#define N_HID   100
#define N_OUT   10
#define BATCH   2048
#define M_TOTAL (BATCH * T_STEPS)   // 204800
#define NPB     112                 // N padded to 14 * 8
#define NK      49                  // 784 / 16 k-chunks

// smem layout (per stage), 48-byte row pitch => conflict-free ldmatrix
#define SA        48
#define A_HI_OFF  0
#define A_LO_OFF  (128 * SA)                  // 6144
#define B_HI_OFF  (2 * 128 * SA)              // 12288
#define B_LO_OFF  (B_HI_OFF + NPB * SA)       // 17664
#define STAGE     (B_LO_OFF + NPB * SA)       // 23040
#define SMEM_TOTAL (2 * STAGE)                // 46080

__device__ __align__(16) float  g_cur1[(size_t)M_TOTAL * N_HID];  // 82 MB scratch
__device__ __align__(16) __half g_w1h[NPB * N_IN];
__device__ __align__(16) __half g_w1l[NPB * N_IN];
__device__ int g_prof_sink;

// ---------------------------------------------------------------------------
__device__ __forceinline__ uint32_t smem_u32(const void* p) {
    uint32_t a;
    asm("{ .reg .u64 t; cvta.to.shared.u64 t, %1; cvt.u32.u64 %0, t; }" : "=r"(a) : "l"(p));
    return a;
}

#define LDSM4(r, addr)                                                          \
    asm volatile("ldmatrix.sync.aligned.m8n8.x4.shared.b16 {%0,%1,%2,%3}, [%4];" \
        : "=r"((r)[0]), "=r"((r)[1]), "=r"((r)[2]), "=r"((r)[3]) : "r"(addr))

#define LDSM2(r, addr)                                                          \
    asm volatile("ldmatrix.sync.aligned.m8n8.x2.shared.b16 {%0,%1}, [%2];"      \
        : "=r"((r)[0]), "=r"((r)[1]) : "r"(addr))

#define MMA16816(d, a, b0, b1)                                                  \
    asm volatile("mma.sync.aligned.m16n8k16.row.col.f32.f16.f16.f32 "           \
        "{%0,%1,%2,%3}, {%4,%5,%6,%7}, {%8,%9}, {%0,%1,%2,%3};"                 \
        : "+f"((d)[0]), "+f"((d)[1]), "+f"((d)[2]), "+f"((d)[3])                \
        : "r"((a)[0]), "r"((a)[1]), "r"((a)[2]), "r"((a)[3]), "r"(b0), "r"(b1))

// ---------------------------------------------------------------------------
__global__ void prof_shift() {
    if (threadIdx.x == 0) g_prof_sink = 1;
}

// ---------------------------------------------------------------------------
// Kernel 0: split W1 into fp16 hi/lo (Dekker split), zero-padded to [112][784]
// ---------------------------------------------------------------------------
__global__ void w1_split(const float* __restrict__ W1) {
    int idx = blockIdx.x * 256 + threadIdx.x;
    if (idx >= NPB * N_IN) return;
    int n = idx / N_IN, k = idx % N_IN;
    float v = (n < N_HID) ? W1[n * N_IN + k] : 0.0f;
    __half h = __float2half_rn(v);
    g_w1h[idx] = h;
    g_w1l[idx] = __float2half_rn(v - __half2float(h));
}

// ---------------------------------------------------------------------------
// Kernel 1: cur1 = x @ W1^T + b1 via mma.sync fp16 3-product split.
// (identical to the 306 us measured config: 256 thr, M=128 x N=112, 4x2 grid)
// ---------------------------------------------------------------------------
extern __shared__ char sm_buf[];

__global__ void __launch_bounds__(256, 2) izh_gemm_hmma(
    const float* __restrict__ x, const float* __restrict__ b1)
{
    const int tid    = threadIdx.x;
    const int wid    = tid >> 5;
    const int lane   = tid & 31;
    const int warp_m = wid >> 1;        // 0..3
    const int warp_n = wid & 1;         // 0..1
    const int row0   = blockIdx.x * 128;

    const uint32_t sb = smem_u32(sm_buf);

    const uint32_t aLane = (uint32_t)((lane & 15) * SA + (lane >> 4) * 16);
    const uint32_t bLane = (uint32_t)((((lane & 7) + ((lane >> 4) << 3)) * SA) +
                                      (((lane >> 3) & 1) * 16));
    const uint32_t aWarp = (uint32_t)(warp_m * 32 * SA);
    const uint32_t bWarp = (uint32_t)(warp_n * 56 * SA);

    float acc[2][7][4];
    #pragma unroll
    for (int mt = 0; mt < 2; mt++)
        #pragma unroll
        for (int nt = 0; nt < 7; nt++)
            #pragma unroll
            for (int i = 0; i < 4; i++)
                acc[mt][nt][i] = 0.0f;

    float4 aReg[2];
    uint4  bReg[2] = {};

    auto load_chunk = [&](int c) {
        const int k0 = c * 16;
        #pragma unroll
        for (int i = 0; i < 2; i++) {
            int id  = tid + i * 256;          // 0..511
            int row = id >> 2, q = id & 3;
            aReg[i] = *(const float4*)(x + (size_t)(row0 + row) * N_IN + k0 + q * 4);
        }
        #pragma unroll
        for (int i = 0; i < 2; i++) {
            int id = tid + i * 256;
            if (id < 448) {
                int half = id / 224, j = id % 224;
                int row = j >> 1, part = j & 1;
                const __half* src = (half == 0 ? g_w1h : g_w1l) + row * N_IN + k0 + part * 8;
                bReg[i] = *(const uint4*)src;
            }
        }
    };

    auto store_chunk = [&](int s) {
        char* st = sm_buf + s * STAGE;
        #pragma unroll
        for (int i = 0; i < 2; i++) {
            int id  = tid + i * 256;
            int row = id >> 2, q = id & 3;
            float4 v = aReg[i];
            __half2 h0 = __floats2half2_rn(v.x, v.y);
            __half2 h1 = __floats2half2_rn(v.z, v.w);
            float2 f0 = __half22float2(h0), f1 = __half22float2(h1);
            __half2 l0 = __floats2half2_rn(v.x - f0.x, v.y - f0.y);
            __half2 l1 = __floats2half2_rn(v.z - f1.x, v.w - f1.y);
            uint32_t off = (uint32_t)(row * SA + q * 8);
            *(uint2*)(st + A_HI_OFF + off) = make_uint2(*(uint32_t*)&h0, *(uint32_t*)&h1);
            *(uint2*)(st + A_LO_OFF + off) = make_uint2(*(uint32_t*)&l0, *(uint32_t*)&l1);
        }
        #pragma unroll
        for (int i = 0; i < 2; i++) {
            int id = tid + i * 256;
            if (id < 448) {
                int half = id / 224, j = id % 224;
                int row = j >> 1, part = j & 1;
                *(uint4*)(st + (half == 0 ? B_HI_OFF : B_LO_OFF) + row * SA + part * 16) = bReg[i];
            }
        }
    };

    auto compute = [&](int s) {
        const uint32_t stage = sb + s * STAGE;
        uint32_t ahi[2][4], alo[2][4];
        #pragma unroll
        for (int mt = 0; mt < 2; mt++) {
            uint32_t addr = stage + A_HI_OFF + aWarp + mt * 16 * SA + aLane;
            LDSM4(ahi[mt], addr);
            LDSM4(alo[mt], addr + (A_LO_OFF - A_HI_OFF));
        }
        #pragma unroll
        for (int p = 0; p < 3; p++) {
            uint32_t bh[4], bl[4];
            uint32_t addr = stage + B_HI_OFF + bWarp + p * 16 * SA + bLane;
            LDSM4(bh, addr);
            LDSM4(bl, addr + NPB * SA);
            #pragma unroll
            for (int mt = 0; mt < 2; mt++)
                #pragma unroll
                for (int q = 0; q < 2; q++)
                    MMA16816(acc[mt][p * 2 + q], ahi[mt], bh[2 * q], bh[2 * q + 1]);
            #pragma unroll
            for (int mt = 0; mt < 2; mt++)
                #pragma unroll
                for (int q = 0; q < 2; q++)
                    MMA16816(acc[mt][p * 2 + q], ahi[mt], bl[2 * q], bl[2 * q + 1]);
            #pragma unroll
            for (int mt = 0; mt < 2; mt++)
                #pragma unroll
                for (int q = 0; q < 2; q++)
                    MMA16816(acc[mt][p * 2 + q], alo[mt], bh[2 * q], bh[2 * q + 1]);
        }
        {
            uint32_t bh[2], bl[2];
            uint32_t addr = stage + B_HI_OFF + bWarp + 48 * SA + bLane;
            LDSM2(bh, addr);
            LDSM2(bl, addr + NPB * SA);
            #pragma unroll
            for (int mt = 0; mt < 2; mt++)
                MMA16816(acc[mt][6], ahi[mt], bh[0], bh[1]);
            #pragma unroll
            for (int mt = 0; mt < 2; mt++)
                MMA16816(acc[mt][6], ahi[mt], bl[0], bl[1]);
            #pragma unroll
            for (int mt = 0; mt < 2; mt++)
                MMA16816(acc[mt][6], alo[mt], bh[0], bh[1]);
        }
    };

    load_chunk(0);
    store_chunk(0);
    for (int c = 0; c < NK; c++) {
        __syncthreads();
        if (c + 1 < NK) load_chunk(c + 1);
        compute(c & 1);
        if (c + 1 < NK) store_chunk((c + 1) & 1);
    }

    #pragma unroll
    for (int mt = 0; mt < 2; mt++) {
        int rbase = row0 + warp_m * 32 + mt * 16 + (lane >> 2);
        #pragma unroll
        for (int nt = 0; nt < 7; nt++) {
            int col = warp_n * 56 + nt * 8 + (lane & 3) * 2;
            if (col < N_HID) {
                float bb0 = __ldg(b1 + col), bb1 = __ldg(b1 + col + 1);
                float2 v0 = make_float2(acc[mt][nt][0] + bb0, acc[mt][nt][1] + bb1);
                float2 v1 = make_float2(acc[mt][nt][2] + bb0, acc[mt][nt][3] + bb1);
                *(float2*)(g_cur1 + (size_t)rbase * N_HID + col)       = v0;
                *(float2*)(g_cur1 + (size_t)(rbase + 8) * N_HID + col) = v1;
            }
        }
    }
}

// ---------------------------------------------------------------------------
// Kernel 2: Izhikevich dynamics — one warp handles TWO batch rows.
// The two rows are fully independent chains sharing the warp's issue slots:
// stalls in row A's serial chain are filled by row B's instructions (ILP x2).
// W2/b2 registers shared; per-row state/spike buffers separate. Per-row FMA
// order identical to loop3 => bit-identical results.
// ---------------------------------------------------------------------------
__global__ __launch_bounds__(32) void izh_loop7(
    const float* __restrict__ W2, const float* __restrict__ b2,
    float* __restrict__ out)
{
    const float A = 0.02f, Bp = 0.2f, Cp = -65.0f, Dp = 8.0f, THR = 0.03f;
    const int b0 = blockIdx.x * 2;
    const int b1 = b0 + 1;
    const int l  = threadIdx.x;
    const int h0 = l * 4;
    const bool hv = (h0 < N_HID);      // lanes 0..24 hold hidden state

    __shared__ float spA[112], spB[112];

    const int o  = l % N_OUT;
    const int ch = (l < 30) ? (l / 10) : 0;
    float wreg[36];
    #pragma unroll
    for (int j = 0; j < 36; j++) {
        int h = 32 * ch + j;
        bool own = (l < 30) && (h < N_HID) && (ch == 0 || j >= 4);
        wreg[j] = own ? W2[o * N_HID + h] : 0.0f;
    }
    const float bb = (l < N_OUT) ? b2[l] : 0.0f;

    float v1a[4], u1a[4], v1b[4], u1b[4];
    #pragma unroll
    for (int i = 0; i < 4; i++) {
        v1a[i] = -70.0f; u1a[i] = -15.0f;
        v1b[i] = -70.0f; u1b[i] = -15.0f;
    }
    float v2a = -70.0f, u2a = -15.0f;
    float v2b = -70.0f, u2b = -15.0f;

    const float* curpA = g_cur1 + (size_t)b0 * T_STEPS * N_HID;
    const float* curpB = g_cur1 + (size_t)b1 * T_STEPS * N_HID;
    const size_t mem_off = (size_t)T_STEPS * BATCH * N_OUT;

    float4 IA = hv ? *(const float4*)(curpA + h0) : make_float4(0.f, 0.f, 0.f, 0.f);
    float4 IB = hv ? *(const float4*)(curpB + h0) : make_float4(0.f, 0.f, 0.f, 0.f);

    for (int t = 0; t < T_STEPS; t++) {
        float4 InA = make_float4(0.f, 0.f, 0.f, 0.f);
        float4 InB = make_float4(0.f, 0.f, 0.f, 0.f);
        if (t + 1 < T_STEPS && hv) {
            InA = *(const float4*)(curpA + (size_t)(t + 1) * N_HID + h0);
            InB = *(const float4*)(curpB + (size_t)(t + 1) * N_HID + h0);
        }

        // ---- layer-1 dynamics, both rows (independent chains) ----
        if (hv) {
            float IaA[4] = {IA.x, IA.y, IA.z, IA.w};
            float IaB[4] = {IB.x, IB.y, IB.z, IB.w};
            float sA[4], sB[4];
            #pragma unroll
            for (int i = 0; i < 4; i++) {
                float vnA = v1a[i] + 0.04f * v1a[i] * v1a[i] + 5.0f * v1a[i] + 140.0f - u1a[i] + IaA[i];
                float unA = u1a[i] + A * (Bp * v1a[i] - u1a[i]);
                float vnB = v1b[i] + 0.04f * v1b[i] * v1b[i] + 5.0f * v1b[i] + 140.0f - u1b[i] + IaB[i];
                float unB = u1b[i] + A * (Bp * v1b[i] - u1b[i]);
                float qA = (vnA >= THR) ? 1.0f : 0.0f;
                float qB = (vnB >= THR) ? 1.0f : 0.0f;
                v1a[i] = (qA > 0.0f) ? Cp : vnA;
                u1a[i] = (qA > 0.0f) ? (unA + Dp) : unA;
                v1b[i] = (qB > 0.0f) ? Cp : vnB;
                u1b[i] = (qB > 0.0f) ? (unB + Dp) : unB;
                sA[i] = qA;
                sB[i] = qB;
            }
            *(float4*)(spA + h0) = make_float4(sA[0], sA[1], sA[2], sA[3]);
            *(float4*)(spB + h0) = make_float4(sB[0], sB[1], sB[2], sB[3]);
        }
        __syncwarp();

        // ---- layer-2 partial dots, both rows ----
        float a0 = 0.f, a1 = 0.f, a2 = 0.f, a3 = 0.f;
        float c0 = 0.f, c1 = 0.f, c2s = 0.f, c3 = 0.f;
        const float4* sA4 = (const float4*)(spA + 32 * ch);
        const float4* sB4 = (const float4*)(spB + 32 * ch);
        #pragma unroll
        for (int j = 0; j < 9; j++) {
            float4 va = sA4[j];
            float4 vb = sB4[j];
            a0  += va.x * wreg[4 * j + 0];
            a1  += va.y * wreg[4 * j + 1];
            a2  += va.z * wreg[4 * j + 2];
            a3  += va.w * wreg[4 * j + 3];
            c0  += vb.x * wreg[4 * j + 0];
            c1  += vb.y * wreg[4 * j + 1];
            c2s += vb.z * wreg[4 * j + 2];
            c3  += vb.w * wreg[4 * j + 3];
        }
        float pA = (a0 + a1) + (a2 + a3);
        float pB = (c0 + c1) + (c2s + c3);
        float qA1 = __shfl_down_sync(0xFFFFFFFFu, pA, 10);
        float qB1 = __shfl_down_sync(0xFFFFFFFFu, pB, 10);
        float qA2 = __shfl_down_sync(0xFFFFFFFFu, pA, 20);
        float qB2 = __shfl_down_sync(0xFFFFFFFFu, pB, 20);

        if (l < N_OUT) {
            float cA = pA + qA1 + qA2 + bb;
            float cB = pB + qB1 + qB2 + bb;
            float vnA = v2a + 0.04f * v2a * v2a + 5.0f * v2a + 140.0f - u2a + cA;
            float unA = u2a + A * (Bp * v2a - u2a);
            float vnB = v2b + 0.04f * v2b * v2b + 5.0f * v2b + 140.0f - u2b + cB;
            float unB = u2b + A * (Bp * v2b - u2b);
            float qA = (vnA >= THR) ? 1.0f : 0.0f;
            float qB = (vnB >= THR) ? 1.0f : 0.0f;
            v2a = (qA > 0.0f) ? Cp : vnA;
            u2a = (qA > 0.0f) ? (unA + Dp) : unA;
            v2b = (qB > 0.0f) ? Cp : vnB;
            u2b = (qB > 0.0f) ? (unB + Dp) : unB;
            size_t ooA = ((size_t)t * BATCH + b0) * N_OUT + l;
            size_t ooB = ((size_t)t * BATCH + b1) * N_OUT + l;
            out[ooA]           = qA;
            out[mem_off + ooA] = v2a;
            out[ooB]           = qB;
            out[mem_off + ooB] = v2b;
        }
        __syncwarp();   // spks reads done before next step overwrites
        IA = InA;
        IB = InB;
    }
}

// ---------------------------------------------------------------------------
extern "C" void kernel_launch(void* const* d_in, const int* in_sizes, int n_in,
                              void* d_out, int out_size)
{
    const float* x  = (const float*)d_in[0];
    const float* W1 = (const float*)d_in[1];
    const float* b1 = (const float*)d_in[2];
    const float* W2 = (const float*)d_in[3];
    const float* b2 = (const float*)d_in[4];
    float* out = (float*)d_out;
    (void)in_sizes; (void)n_in; (void)out_size;

    // 6 launches; capture index ≡ 3 (mod 6) -> LOOP profiled
    prof_shift<<<1, 32>>>();                                      // pos 0
    w1_split<<<(NPB * N_IN + 255) / 256, 256>>>(W1);              // pos 1
    izh_gemm_hmma<<<M_TOTAL / 128, 256, SMEM_TOTAL>>>(x, b1);     // pos 2
    izh_loop7<<<BATCH / 2, 32>>>(W2, b2, out);                    // pos 3
    prof_shift<<<1, 32>>>();                                      // pos 4
    prof_shift<<<1, 32>>>();                                      // pos 5
}

// round 16
// speedup vs baseline: 1.0142x; 1.0142x over previous
#include <cuda_runtime.h>
#include <cuda_fp16.h>
#include <cstdint>

#define T_STEPS 100
#define N_IN    784
#define N_HID   100
#define N_OUT   10
#define BATCH   2048
#define M_TOTAL (BATCH * T_STEPS)   // 204800
#define NPB     112                 // N padded to 14 * 8
#define KC      32                  // K per pipeline chunk
#define NC      25                  // 24 full KC32 chunks + 1 tail KC16

// smem layout (per stage), 80-byte row pitch (64B data + 16B pad)
// 80r mod 128 hits distinct 16B granules for r=0..7 => ldmatrix conflict-free
#define SAW       80
#define A_HI_OFF  0
#define A_LO_OFF  (128 * SAW)                 // 10240
#define B_HI_OFF  (2 * 128 * SAW)             // 20480
#define B_LO_OFF  (B_HI_OFF + NPB * SAW)      // 29440
#define STAGE     (B_LO_OFF + NPB * SAW)      // 38400
#define SMEM_TOTAL (2 * STAGE)                // 76800

__device__ __align__(16) float  g_cur1[(size_t)M_TOTAL * N_HID];  // 82 MB scratch
__device__ __align__(16) __half g_w1h[NPB * N_IN];
__device__ __align__(16) __half g_w1l[NPB * N_IN];
__device__ int g_prof_sink;

// ---------------------------------------------------------------------------
__device__ __forceinline__ uint32_t smem_u32(const void* p) {
    uint32_t a;
    asm("{ .reg .u64 t; cvta.to.shared.u64 t, %1; cvt.u32.u64 %0, t; }" : "=r"(a) : "l"(p));
    return a;
}

#define LDSM4(r, addr)                                                          \
    asm volatile("ldmatrix.sync.aligned.m8n8.x4.shared.b16 {%0,%1,%2,%3}, [%4];" \
        : "=r"((r)[0]), "=r"((r)[1]), "=r"((r)[2]), "=r"((r)[3]) : "r"(addr))

#define LDSM2(r, addr)                                                          \
    asm volatile("ldmatrix.sync.aligned.m8n8.x2.shared.b16 {%0,%1}, [%2];"      \
        : "=r"((r)[0]), "=r"((r)[1]) : "r"(addr))

#define MMA16816(d, a, b0, b1)                                                  \
    asm volatile("mma.sync.aligned.m16n8k16.row.col.f32.f16.f16.f32 "           \
        "{%0,%1,%2,%3}, {%4,%5,%6,%7}, {%8,%9}, {%0,%1,%2,%3};"                 \
        : "+f"((d)[0]), "+f"((d)[1]), "+f"((d)[2]), "+f"((d)[3])                \
        : "r"((a)[0]), "r"((a)[1]), "r"((a)[2]), "r"((a)[3]), "r"(b0), "r"(b1))

// ---------------------------------------------------------------------------
__global__ void prof_shift() {
    if (threadIdx.x == 0) g_prof_sink = 1;
}

// ---------------------------------------------------------------------------
// Kernel 0: split W1 into fp16 hi/lo (Dekker split), zero-padded to [112][784]
// ---------------------------------------------------------------------------
__global__ void w1_split(const float* __restrict__ W1) {
    int idx = blockIdx.x * 256 + threadIdx.x;
    if (idx >= NPB * N_IN) return;
    int n = idx / N_IN, k = idx % N_IN;
    float v = (n < N_HID) ? W1[n * N_IN + k] : 0.0f;
    __half h = __float2half_rn(v);
    g_w1h[idx] = h;
    g_w1l[idx] = __float2half_rn(v - __half2float(h));
}

// ---------------------------------------------------------------------------
// Kernel 1: cur1 = x @ W1^T + b1 via mma.sync fp16 3-product split.
// CTA: 256 thr, tile M=128 x N=112, K in 32-chunks (two k16 halves), ONE
// barrier per 32-K (25 vs 49). Two load/store rounds per chunk reuse the
// same 16 prefetch registers; round 1 overlaps compute of k-half 0.
// Same k-accumulation order as the KC=16 version => bit-identical.
// ---------------------------------------------------------------------------
extern __shared__ char sm_buf[];

__global__ void __launch_bounds__(256, 2) izh_gemm_hmma(
    const float* __restrict__ x, const float* __restrict__ b1)
{
    const int tid    = threadIdx.x;
    const int wid    = tid >> 5;
    const int lane   = tid & 31;
    const int warp_m = wid >> 1;        // 0..3
    const int warp_n = wid & 1;         // 0..1
    const int row0   = blockIdx.x * 128;

    const uint32_t sb = smem_u32(sm_buf);

    const uint32_t aLane = (uint32_t)((lane & 15) * SAW + (lane >> 4) * 16);
    const uint32_t bLane = (uint32_t)((((lane & 7) + ((lane >> 4) << 3)) * SAW) +
                                      (((lane >> 3) & 1) * 16));
    const uint32_t aWarp = (uint32_t)(warp_m * 32 * SAW);
    const uint32_t bWarp = (uint32_t)(warp_n * 56 * SAW);

    float acc[2][7][4];
    #pragma unroll
    for (int mt = 0; mt < 2; mt++)
        #pragma unroll
        for (int nt = 0; nt < 7; nt++)
            #pragma unroll
            for (int i = 0; i < 4; i++)
                acc[mt][nt][i] = 0.0f;

    float4 aReg[2];
    uint4  bReg[2];

    // ---- A loads: 1024 slots/chunk (128 rows x 8 float4); round r covers
    //      slots r*512 + {tid, tid+256}.
    auto loadA = [&](int c, int r) {
        const int k0 = c * KC;
        #pragma unroll
        for (int i = 0; i < 2; i++) {
            int id  = r * 512 + i * 256 + tid;
            int row = id >> 3, q = id & 7;
            int kg  = k0 + q * 4;
            aReg[i] = (kg < N_IN)
                ? *(const float4*)(x + (size_t)(row0 + row) * N_IN + kg)
                : make_float4(0.f, 0.f, 0.f, 0.f);
        }
    };
    auto storeA = [&](int s, int r) {
        char* st = sm_buf + s * STAGE;
        #pragma unroll
        for (int i = 0; i < 2; i++) {
            int id  = r * 512 + i * 256 + tid;
            int row = id >> 3, q = id & 7;
            float4 v = aReg[i];
            __half2 h0 = __floats2half2_rn(v.x, v.y);
            __half2 h1 = __floats2half2_rn(v.z, v.w);
            float2 f0 = __half22float2(h0), f1 = __half22float2(h1);
            __half2 l0 = __floats2half2_rn(v.x - f0.x, v.y - f0.y);
            __half2 l1 = __floats2half2_rn(v.z - f1.x, v.w - f1.y);
            uint32_t off = (uint32_t)(row * SAW + q * 8);
            *(uint2*)(st + A_HI_OFF + off) = make_uint2(*(uint32_t*)&h0, *(uint32_t*)&h1);
            *(uint2*)(st + A_LO_OFF + off) = make_uint2(*(uint32_t*)&l0, *(uint32_t*)&l1);
        }
    };

    // ---- B loads: 896 slots/chunk (2 halves x 112 rows x 4 parts of 16B);
    //      round 0 = hi half (slots 0..447), round 1 = lo half (448..895);
    //      within a round: {tid, tid+256 (tid<192)}.
    auto loadB = [&](int c, int r) {
        const int k0 = c * KC;
        #pragma unroll
        for (int i = 0; i < 2; i++) {
            int rel = i * 256 + tid;
            if (rel < 448) {
                int row = rel >> 2, part = rel & 3;
                int kg  = k0 + part * 8;
                const __half* src = (r == 0 ? g_w1h : g_w1l) + row * N_IN + kg;
                bReg[i] = (kg < N_IN) ? *(const uint4*)src
                                      : make_uint4(0u, 0u, 0u, 0u);
            }
        }
    };
    auto storeB = [&](int s, int r) {
        char* st = sm_buf + s * STAGE + (r == 0 ? B_HI_OFF : B_LO_OFF);
        #pragma unroll
        for (int i = 0; i < 2; i++) {
            int rel = i * 256 + tid;
            if (rel < 448) {
                int row = rel >> 2, part = rel & 3;
                *(uint4*)(st + row * SAW + part * 16) = bReg[i];
            }
        }
    };

    // ---- mma for one k16 half h (0 or 1) of stage s ----
    auto compute = [&](int s, int h) {
        const uint32_t stage = sb + s * STAGE;
        const uint32_t hOff  = (uint32_t)(h * 32);
        uint32_t ahi[2][4], alo[2][4];
        #pragma unroll
        for (int mt = 0; mt < 2; mt++) {
            uint32_t addr = stage + A_HI_OFF + aWarp + mt * 16 * SAW + aLane + hOff;
            LDSM4(ahi[mt], addr);
            LDSM4(alo[mt], addr + (A_LO_OFF - A_HI_OFF));
        }
        #pragma unroll
        for (int p = 0; p < 3; p++) {
            uint32_t bh[4], bl[4];
            uint32_t addr = stage + B_HI_OFF + bWarp + p * 16 * SAW + bLane + hOff;
            LDSM4(bh, addr);
            LDSM4(bl, addr + (B_LO_OFF - B_HI_OFF));
            #pragma unroll
            for (int mt = 0; mt < 2; mt++)
                #pragma unroll
                for (int q = 0; q < 2; q++)
                    MMA16816(acc[mt][p * 2 + q], ahi[mt], bh[2 * q], bh[2 * q + 1]);
            #pragma unroll
            for (int mt = 0; mt < 2; mt++)
                #pragma unroll
                for (int q = 0; q < 2; q++)
                    MMA16816(acc[mt][p * 2 + q], ahi[mt], bl[2 * q], bl[2 * q + 1]);
            #pragma unroll
            for (int mt = 0; mt < 2; mt++)
                #pragma unroll
                for (int q = 0; q < 2; q++)
                    MMA16816(acc[mt][p * 2 + q], alo[mt], bh[2 * q], bh[2 * q + 1]);
        }
        {
            uint32_t bh[2], bl[2];
            uint32_t addr = stage + B_HI_OFF + bWarp + 48 * SAW + bLane + hOff;
            LDSM2(bh, addr);
            LDSM2(bl, addr + (B_LO_OFF - B_HI_OFF));
            #pragma unroll
            for (int mt = 0; mt < 2; mt++)
                MMA16816(acc[mt][6], ahi[mt], bh[0], bh[1]);
            #pragma unroll
            for (int mt = 0; mt < 2; mt++)
                MMA16816(acc[mt][6], ahi[mt], bl[0], bl[1]);
            #pragma unroll
            for (int mt = 0; mt < 2; mt++)
                MMA16816(acc[mt][6], alo[mt], bh[0], bh[1]);
        }
    };

    // ---- prologue: fully stage chunk 0 ----
    loadA(0, 0); loadB(0, 0); storeA(0, 0); storeB(0, 0);
    loadA(0, 1); loadB(0, 1); storeA(0, 1); storeB(0, 1);

    // ---- pipeline: one barrier per KC=32 ----
    for (int c = 0; c < NC; c++) {
        __syncthreads();
        const int s   = c & 1;
        const bool nx = (c + 1 < NC);
        if (nx) { loadA(c + 1, 0); loadB(c + 1, 0); }
        compute(s, 0);
        if (nx) {
            storeA(s ^ 1, 0); storeB(s ^ 1, 0);
            loadA(c + 1, 1);  loadB(c + 1, 1);
        }
        if (c < NC - 1) compute(s, 1);       // tail chunk (c=24) has only k-half 0
        if (nx) { storeA(s ^ 1, 1); storeB(s ^ 1, 1); }
    }

    // ---- epilogue: add bias, store valid cols ----
    #pragma unroll
    for (int mt = 0; mt < 2; mt++) {
        int rbase = row0 + warp_m * 32 + mt * 16 + (lane >> 2);
        #pragma unroll
        for (int nt = 0; nt < 7; nt++) {
            int col = warp_n * 56 + nt * 8 + (lane & 3) * 2;
            if (col < N_HID) {
                float bb0 = __ldg(b1 + col), bb1 = __ldg(b1 + col + 1);
                float2 v0 = make_float2(acc[mt][nt][0] + bb0, acc[mt][nt][1] + bb1);
                float2 v1 = make_float2(acc[mt][nt][2] + bb0, acc[mt][nt][3] + bb1);
                *(float2*)(g_cur1 + (size_t)rbase * N_HID + col)       = v0;
                *(float2*)(g_cur1 + (size_t)(rbase + 8) * N_HID + col) = v1;
            }
        }
    }
}

// ---------------------------------------------------------------------------
// Kernel 2: sequential Izhikevich dynamics — one WARP per batch row (loop3,
// the measured-best variant).
// ---------------------------------------------------------------------------
__global__ __launch_bounds__(32) void izh_loop3(
    const float* __restrict__ W2, const float* __restrict__ b2,
    float* __restrict__ out)
{
    const float A = 0.02f, Bp = 0.2f, Cp = -65.0f, Dp = 8.0f, THR = 0.03f;
    const int b = blockIdx.x;
    const int l = threadIdx.x;
    const int h0 = l * 4;
    const bool hv = (h0 < N_HID);

    __shared__ float spks[112];

    const int o  = l % N_OUT;
    const int ch = (l < 30) ? (l / 10) : 0;
    float wreg[36];
    #pragma unroll
    for (int j = 0; j < 36; j++) {
        int h = 32 * ch + j;
        bool own = (l < 30) && (h < N_HID) && (ch == 0 || j >= 4);
        wreg[j] = own ? W2[o * N_HID + h] : 0.0f;
    }
    const float bb = (l < N_OUT) ? b2[l] : 0.0f;

    float v1[4], u1[4];
    #pragma unroll
    for (int i = 0; i < 4; i++) { v1[i] = -70.0f; u1[i] = -15.0f; }
    float v2 = -70.0f, u2 = -15.0f;

    const float* curp = g_cur1 + (size_t)b * T_STEPS * N_HID;
    const size_t mem_off = (size_t)T_STEPS * BATCH * N_OUT;

    float4 I = hv ? *(const float4*)(curp + h0) : make_float4(0.f, 0.f, 0.f, 0.f);

    for (int t = 0; t < T_STEPS; t++) {
        float4 In = make_float4(0.f, 0.f, 0.f, 0.f);
        if (t + 1 < T_STEPS && hv)
            In = *(const float4*)(curp + (size_t)(t + 1) * N_HID + h0);

        if (hv) {
            float Ia[4] = {I.x, I.y, I.z, I.w};
            float s[4];
            #pragma unroll
            for (int i = 0; i < 4; i++) {
                float vn = v1[i] + 0.04f * v1[i] * v1[i] + 5.0f * v1[i] + 140.0f - u1[i] + Ia[i];
                float un = u1[i] + A * (Bp * v1[i] - u1[i]);
                float sp = (vn >= THR) ? 1.0f : 0.0f;
                v1[i] = (sp > 0.0f) ? Cp : vn;
                u1[i] = (sp > 0.0f) ? (un + Dp) : un;
                s[i] = sp;
            }
            *(float4*)(spks + h0) = make_float4(s[0], s[1], s[2], s[3]);
        }
        __syncwarp();

        float a0 = 0.f, a1 = 0.f, a2 = 0.f, a3 = 0.f;
        const float4* sp4 = (const float4*)(spks + 32 * ch);
        #pragma unroll
        for (int j = 0; j < 9; j++) {
            float4 v = sp4[j];
            a0 += v.x * wreg[4 * j + 0];
            a1 += v.y * wreg[4 * j + 1];
            a2 += v.z * wreg[4 * j + 2];
            a3 += v.w * wreg[4 * j + 3];
        }
        float p = (a0 + a1) + (a2 + a3);
        float q1 = __shfl_down_sync(0xFFFFFFFFu, p, 10);
        float q2 = __shfl_down_sync(0xFFFFFFFFu, p, 20);

        if (l < N_OUT) {
            float c2 = p + q1 + q2 + bb;
            float vn = v2 + 0.04f * v2 * v2 + 5.0f * v2 + 140.0f - u2 + c2;
            float un = u2 + A * (Bp * v2 - u2);
            float sp = (vn >= THR) ? 1.0f : 0.0f;
            v2 = (sp > 0.0f) ? Cp : vn;
            u2 = (sp > 0.0f) ? (un + Dp) : un;
            size_t oo = ((size_t)t * BATCH + b) * N_OUT + l;
            out[oo]           = sp;
            out[mem_off + oo] = v2;
        }
        __syncwarp();
        I = In;
    }
}

// ---------------------------------------------------------------------------
extern "C" void kernel_launch(void* const* d_in, const int* in_sizes, int n_in,
                              void* d_out, int out_size)
{
    const float* x  = (const float*)d_in[0];
    const float* W1 = (const float*)d_in[1];
    const float* b1 = (const float*)d_in[2];
    const float* W2 = (const float*)d_in[3];
    const float* b2 = (const float*)d_in[4];
    float* out = (float*)d_out;
    (void)in_sizes; (void)n_in; (void)out_size;

    cudaFuncSetAttribute(izh_gemm_hmma,
                         cudaFuncAttributeMaxDynamicSharedMemorySize, SMEM_TOTAL);

    // 6 launches; capture index ≡ 3 (mod 6) -> GEMM profiled
    prof_shift<<<1, 32>>>();                                      // pos 0
    prof_shift<<<1, 32>>>();                                      // pos 1
    w1_split<<<(NPB * N_IN + 255) / 256, 256>>>(W1);              // pos 2
    izh_gemm_hmma<<<M_TOTAL / 128, 256, SMEM_TOTAL>>>(x, b1);     // pos 3
    prof_shift<<<1, 32>>>();                                      // pos 4
    izh_loop3<<<BATCH, 32>>>(W2, b2, out);                        // pos 5
}

// round 17
// speedup vs baseline: 1.1315x; 1.1157x over previous
#include <cuda_runtime.h>
#include <cuda_fp16.h>
#include <cstdint>

#define T_STEPS 100
#define N_IN    784
#define N_HID   100
#define N_OUT   10
#define BATCH   2048
#define M_TOTAL (BATCH * T_STEPS)   // 204800
#define NPB     112                 // N padded to 14 * 8
#define NK      49                  // 784 / 16 k-chunks

// smem layout (per stage), 48-byte row pitch => conflict-free ldmatrix
#define SA        48
#define A_HI_OFF  0
#define A_LO_OFF  (128 * SA)                  // 6144
#define B_HI_OFF  (2 * 128 * SA)              // 12288
#define B_LO_OFF  (B_HI_OFF + NPB * SA)       // 17664
#define STAGE     (B_LO_OFF + NPB * SA)       // 23040
#define SMEM_TOTAL (2 * STAGE)                // 46080

__device__ __align__(16) float  g_cur1[(size_t)M_TOTAL * N_HID];  // 82 MB scratch
__device__ __align__(16) __half g_w1h[NPB * N_IN];
__device__ __align__(16) __half g_w1l[NPB * N_IN];
__device__ int g_prof_sink;

// ---------------------------------------------------------------------------
__device__ __forceinline__ uint32_t smem_u32(const void* p) {
    uint32_t a;
    asm("{ .reg .u64 t; cvta.to.shared.u64 t, %1; cvt.u32.u64 %0, t; }" : "=r"(a) : "l"(p));
    return a;
}

#define LDSM4(r, addr)                                                          \
    asm volatile("ldmatrix.sync.aligned.m8n8.x4.shared.b16 {%0,%1,%2,%3}, [%4];" \
        : "=r"((r)[0]), "=r"((r)[1]), "=r"((r)[2]), "=r"((r)[3]) : "r"(addr))

#define LDSM2(r, addr)                                                          \
    asm volatile("ldmatrix.sync.aligned.m8n8.x2.shared.b16 {%0,%1}, [%2];"      \
        : "=r"((r)[0]), "=r"((r)[1]) : "r"(addr))

#define MMA16816(d, a, b0, b1)                                                  \
    asm volatile("mma.sync.aligned.m16n8k16.row.col.f32.f16.f16.f32 "           \
        "{%0,%1,%2,%3}, {%4,%5,%6,%7}, {%8,%9}, {%0,%1,%2,%3};"                 \
        : "+f"((d)[0]), "+f"((d)[1]), "+f"((d)[2]), "+f"((d)[3])                \
        : "r"((a)[0]), "r"((a)[1]), "r"((a)[2]), "r"((a)[3]), "r"(b0), "r"(b1))

// ---------------------------------------------------------------------------
__global__ void prof_shift() {
    if (threadIdx.x == 0) g_prof_sink = 1;
}

// ---------------------------------------------------------------------------
// Kernel 0: split W1 into fp16 hi/lo (Dekker split), zero-padded to [112][784]
// ---------------------------------------------------------------------------
__global__ void w1_split(const float* __restrict__ W1) {
    int idx = blockIdx.x * 256 + threadIdx.x;
    if (idx >= NPB * N_IN) return;
    int n = idx / N_IN, k = idx % N_IN;
    float v = (n < N_HID) ? W1[n * N_IN + k] : 0.0f;
    __half h = __float2half_rn(v);
    g_w1h[idx] = h;
    g_w1l[idx] = __float2half_rn(v - __half2float(h));
}

// ---------------------------------------------------------------------------
// Kernel 1: cur1 = x @ W1^T + b1 via mma.sync fp16 3-product split.
// (byte-identical to the measured 306 us config)
// ---------------------------------------------------------------------------
extern __shared__ char sm_buf[];

__global__ void __launch_bounds__(256, 2) izh_gemm_hmma(
    const float* __restrict__ x, const float* __restrict__ b1)
{
    const int tid    = threadIdx.x;
    const int wid    = tid >> 5;
    const int lane   = tid & 31;
    const int warp_m = wid >> 1;        // 0..3
    const int warp_n = wid & 1;         // 0..1
    const int row0   = blockIdx.x * 128;

    const uint32_t sb = smem_u32(sm_buf);

    const uint32_t aLane = (uint32_t)((lane & 15) * SA + (lane >> 4) * 16);
    const uint32_t bLane = (uint32_t)((((lane & 7) + ((lane >> 4) << 3)) * SA) +
                                      (((lane >> 3) & 1) * 16));
    const uint32_t aWarp = (uint32_t)(warp_m * 32 * SA);
    const uint32_t bWarp = (uint32_t)(warp_n * 56 * SA);

    float acc[2][7][4];
    #pragma unroll
    for (int mt = 0; mt < 2; mt++)
        #pragma unroll
        for (int nt = 0; nt < 7; nt++)
            #pragma unroll
            for (int i = 0; i < 4; i++)
                acc[mt][nt][i] = 0.0f;

    float4 aReg[2];
    uint4  bReg[2] = {};

    auto load_chunk = [&](int c) {
        const int k0 = c * 16;
        #pragma unroll
        for (int i = 0; i < 2; i++) {
            int id  = tid + i * 256;          // 0..511
            int row = id >> 2, q = id & 3;
            aReg[i] = *(const float4*)(x + (size_t)(row0 + row) * N_IN + k0 + q * 4);
        }
        #pragma unroll
        for (int i = 0; i < 2; i++) {
            int id = tid + i * 256;
            if (id < 448) {
                int half = id / 224, j = id % 224;
                int row = j >> 1, part = j & 1;
                const __half* src = (half == 0 ? g_w1h : g_w1l) + row * N_IN + k0 + part * 8;
                bReg[i] = *(const uint4*)src;
            }
        }
    };

    auto store_chunk = [&](int s) {
        char* st = sm_buf + s * STAGE;
        #pragma unroll
        for (int i = 0; i < 2; i++) {
            int id  = tid + i * 256;
            int row = id >> 2, q = id & 3;
            float4 v = aReg[i];
            __half2 h0 = __floats2half2_rn(v.x, v.y);
            __half2 h1 = __floats2half2_rn(v.z, v.w);
            float2 f0 = __half22float2(h0), f1 = __half22float2(h1);
            __half2 l0 = __floats2half2_rn(v.x - f0.x, v.y - f0.y);
            __half2 l1 = __floats2half2_rn(v.z - f1.x, v.w - f1.y);
            uint32_t off = (uint32_t)(row * SA + q * 8);
            *(uint2*)(st + A_HI_OFF + off) = make_uint2(*(uint32_t*)&h0, *(uint32_t*)&h1);
            *(uint2*)(st + A_LO_OFF + off) = make_uint2(*(uint32_t*)&l0, *(uint32_t*)&l1);
        }
        #pragma unroll
        for (int i = 0; i < 2; i++) {
            int id = tid + i * 256;
            if (id < 448) {
                int half = id / 224, j = id % 224;
                int row = j >> 1, part = j & 1;
                *(uint4*)(st + (half == 0 ? B_HI_OFF : B_LO_OFF) + row * SA + part * 16) = bReg[i];
            }
        }
    };

    auto compute = [&](int s) {
        const uint32_t stage = sb + s * STAGE;
        uint32_t ahi[2][4], alo[2][4];
        #pragma unroll
        for (int mt = 0; mt < 2; mt++) {
            uint32_t addr = stage + A_HI_OFF + aWarp + mt * 16 * SA + aLane;
            LDSM4(ahi[mt], addr);
            LDSM4(alo[mt], addr + (A_LO_OFF - A_HI_OFF));
        }
        #pragma unroll
        for (int p = 0; p < 3; p++) {
            uint32_t bh[4], bl[4];
            uint32_t addr = stage + B_HI_OFF + bWarp + p * 16 * SA + bLane;
            LDSM4(bh, addr);
            LDSM4(bl, addr + NPB * SA);
            #pragma unroll
            for (int mt = 0; mt < 2; mt++)
                #pragma unroll
                for (int q = 0; q < 2; q++)
                    MMA16816(acc[mt][p * 2 + q], ahi[mt], bh[2 * q], bh[2 * q + 1]);
            #pragma unroll
            for (int mt = 0; mt < 2; mt++)
                #pragma unroll
                for (int q = 0; q < 2; q++)
                    MMA16816(acc[mt][p * 2 + q], ahi[mt], bl[2 * q], bl[2 * q + 1]);
            #pragma unroll
            for (int mt = 0; mt < 2; mt++)
                #pragma unroll
                for (int q = 0; q < 2; q++)
                    MMA16816(acc[mt][p * 2 + q], alo[mt], bh[2 * q], bh[2 * q + 1]);
        }
        {
            uint32_t bh[2], bl[2];
            uint32_t addr = stage + B_HI_OFF + bWarp + 48 * SA + bLane;
            LDSM2(bh, addr);
            LDSM2(bl, addr + NPB * SA);
            #pragma unroll
            for (int mt = 0; mt < 2; mt++)
                MMA16816(acc[mt][6], ahi[mt], bh[0], bh[1]);
            #pragma unroll
            for (int mt = 0; mt < 2; mt++)
                MMA16816(acc[mt][6], ahi[mt], bl[0], bl[1]);
            #pragma unroll
            for (int mt = 0; mt < 2; mt++)
                MMA16816(acc[mt][6], alo[mt], bh[0], bh[1]);
        }
    };

    load_chunk(0);
    store_chunk(0);
    for (int c = 0; c < NK; c++) {
        __syncthreads();
        if (c + 1 < NK) load_chunk(c + 1);
        compute(c & 1);
        if (c + 1 < NK) store_chunk((c + 1) & 1);
    }

    #pragma unroll
    for (int mt = 0; mt < 2; mt++) {
        int rbase = row0 + warp_m * 32 + mt * 16 + (lane >> 2);
        #pragma unroll
        for (int nt = 0; nt < 7; nt++) {
            int col = warp_n * 56 + nt * 8 + (lane & 3) * 2;
            if (col < N_HID) {
                float bb0 = __ldg(b1 + col), bb1 = __ldg(b1 + col + 1);
                float2 v0 = make_float2(acc[mt][nt][0] + bb0, acc[mt][nt][1] + bb1);
                float2 v1 = make_float2(acc[mt][nt][2] + bb0, acc[mt][nt][3] + bb1);
                *(float2*)(g_cur1 + (size_t)rbase * N_HID + col)       = v0;
                *(float2*)(g_cur1 + (size_t)(rbase + 8) * N_HID + col) = v1;
            }
        }
    }
}

// ---------------------------------------------------------------------------
// Kernel 2: Izhikevich dynamics — one WARP per row, TWO TIMESTEPS PER PHASE.
// Straight-line (no hv branches): all 32 lanes run izh; pad lanes (25..31)
// use a clamped load index and write spks[100..127] padding. Two spike
// buffers per phase, ONE syncwarp between produce and consume, dots for the
// two steps interleaved for ILP. Per-step FMA order identical to loop3.
// ---------------------------------------------------------------------------
__global__ __launch_bounds__(32) void izh_loop8(
    const float* __restrict__ W2, const float* __restrict__ b2,
    float* __restrict__ out)
{
    const float A = 0.02f, Bp = 0.2f, Cp = -65.0f, Dp = 8.0f, THR = 0.03f;
    const int b = blockIdx.x;
    const int l = threadIdx.x;
    const int h0 = l * 4;
    const bool hv = (h0 < N_HID);
    const int hc = hv ? h0 : 0;          // clamped load index (no branch)

    __shared__ float spA[128], spB[128];

    const int o  = l % N_OUT;
    const int ch = (l < 30) ? (l / 10) : 0;
    float wreg[36];
    #pragma unroll
    for (int j = 0; j < 36; j++) {
        int h = 32 * ch + j;
        bool own = (l < 30) && (h < N_HID) && (ch == 0 || j >= 4);
        wreg[j] = own ? W2[o * N_HID + h] : 0.0f;
    }
    const float bb = (l < N_OUT) ? b2[l] : 0.0f;

    float v1[4], u1[4];
    #pragma unroll
    for (int i = 0; i < 4; i++) { v1[i] = -70.0f; u1[i] = -15.0f; }
    float v2 = -70.0f, u2 = -15.0f;

    const float* curp = g_cur1 + (size_t)b * T_STEPS * N_HID;
    const size_t mem_off = (size_t)T_STEPS * BATCH * N_OUT;

    float4 I0 = *(const float4*)(curp + hc);
    float4 I1 = *(const float4*)(curp + N_HID + hc);

    // one izh step for 4 neurons; writes spikes to sp
    auto izh1 = [&](float4 I, float* sp) {
        float Ia[4] = {I.x, I.y, I.z, I.w};
        float s[4];
        #pragma unroll
        for (int i = 0; i < 4; i++) {
            float vn = v1[i] + 0.04f * v1[i] * v1[i] + 5.0f * v1[i] + 140.0f - u1[i] + Ia[i];
            float un = u1[i] + A * (Bp * v1[i] - u1[i]);
            float sq = (vn >= THR) ? 1.0f : 0.0f;
            v1[i] = (sq > 0.0f) ? Cp : vn;
            u1[i] = (sq > 0.0f) ? (un + Dp) : un;
            s[i] = sq;
        }
        *(float4*)(sp + h0) = make_float4(s[0], s[1], s[2], s[3]);
    };

    for (int t = 0; t < T_STEPS; t += 2) {
        // prefetch next pair
        float4 P0 = make_float4(0.f, 0.f, 0.f, 0.f);
        float4 P1 = make_float4(0.f, 0.f, 0.f, 0.f);
        if (t + 2 < T_STEPS) P0 = *(const float4*)(curp + (size_t)(t + 2) * N_HID + hc);
        if (t + 3 < T_STEPS) P1 = *(const float4*)(curp + (size_t)(t + 3) * N_HID + hc);

        // two local izh steps (short serial v1 chain), two spike buffers
        izh1(I0, spA);
        izh1(I1, spB);
        __syncwarp();

        // two dots, interleaved for ILP
        float a0 = 0.f, a1 = 0.f, a2 = 0.f, a3 = 0.f;
        float c0 = 0.f, c1 = 0.f, c2x = 0.f, c3 = 0.f;
        const float4* sA4 = (const float4*)(spA + 32 * ch);
        const float4* sB4 = (const float4*)(spB + 32 * ch);
        #pragma unroll
        for (int j = 0; j < 9; j++) {
            float4 va = sA4[j];
            float4 vb = sB4[j];
            a0  += va.x * wreg[4 * j + 0];
            a1  += va.y * wreg[4 * j + 1];
            a2  += va.z * wreg[4 * j + 2];
            a3  += va.w * wreg[4 * j + 3];
            c0  += vb.x * wreg[4 * j + 0];
            c1  += vb.y * wreg[4 * j + 1];
            c2x += vb.z * wreg[4 * j + 2];
            c3  += vb.w * wreg[4 * j + 3];
        }
        float pA = (a0 + a1) + (a2 + a3);
        float pB = (c0 + c1) + (c2x + c3);
        float qA1 = __shfl_down_sync(0xFFFFFFFFu, pA, 10);
        float qB1 = __shfl_down_sync(0xFFFFFFFFu, pB, 10);
        float qA2 = __shfl_down_sync(0xFFFFFFFFu, pA, 20);
        float qB2 = __shfl_down_sync(0xFFFFFFFFu, pB, 20);

        // layer-2: step t then t+1 (short serial chain), stores predicated
        {
            float cA = pA + qA1 + qA2 + bb;
            float vn = v2 + 0.04f * v2 * v2 + 5.0f * v2 + 140.0f - u2 + cA;
            float un = u2 + A * (Bp * v2 - u2);
            float sq = (vn >= THR) ? 1.0f : 0.0f;
            v2 = (sq > 0.0f) ? Cp : vn;
            u2 = (sq > 0.0f) ? (un + Dp) : un;
            if (l < N_OUT) {
                size_t oo = ((size_t)t * BATCH + b) * N_OUT + l;
                out[oo]           = sq;
                out[mem_off + oo] = v2;
            }
        }
        {
            float cB = pB + qB1 + qB2 + bb;
            float vn = v2 + 0.04f * v2 * v2 + 5.0f * v2 + 140.0f - u2 + cB;
            float un = u2 + A * (Bp * v2 - u2);
            float sq = (vn >= THR) ? 1.0f : 0.0f;
            v2 = (sq > 0.0f) ? Cp : vn;
            u2 = (sq > 0.0f) ? (un + Dp) : un;
            if (l < N_OUT) {
                size_t oo = ((size_t)(t + 1) * BATCH + b) * N_OUT + l;
                out[oo]           = sq;
                out[mem_off + oo] = v2;
            }
        }
        __syncwarp();     // all reads of spA/spB done before next phase writes
        I0 = P0;
        I1 = P1;
    }
}

// ---------------------------------------------------------------------------
extern "C" void kernel_launch(void* const* d_in, const int* in_sizes, int n_in,
                              void* d_out, int out_size)
{
    const float* x  = (const float*)d_in[0];
    const float* W1 = (const float*)d_in[1];
    const float* b1 = (const float*)d_in[2];
    const float* W2 = (const float*)d_in[3];
    const float* b2 = (const float*)d_in[4];
    float* out = (float*)d_out;
    (void)in_sizes; (void)n_in; (void)out_size;

    // 6 launches; capture index ≡ 3 (mod 6) -> LOOP profiled
    prof_shift<<<1, 32>>>();                                      // pos 0
    w1_split<<<(NPB * N_IN + 255) / 256, 256>>>(W1);              // pos 1
    izh_gemm_hmma<<<M_TOTAL / 128, 256, SMEM_TOTAL>>>(x, b1);     // pos 2
    izh_loop8<<<BATCH, 32>>>(W2, b2, out);                        // pos 3
    prof_shift<<<1, 32>>>();                                      // pos 4
    prof_shift<<<1, 32>>>();                                      // pos 5
}